// round 8
// baseline (speedup 1.0000x reference)
#include <cuda_runtime.h>
#include <cuda_bf16.h>
#include <math.h>
#include <stdint.h>

#define NN  10000   // nodes
#define NE  50000   // edges
#define HD  64      // hidden
#define BG  256     // batch graphs
#define NEF 4
#define NNF 11
#define NTG 12      // targets
#define IC  128     // 2H
#define KZ  4160    // 64*65 : Zcat columns (64i x 64k + 64 hsum)

// ---------------- scratch (static device globals; no allocation) ----------------
__device__ float g_e1[NE * HD];
__device__ __nv_bfloat16 g_zh[(size_t)NN * KZ];        // 83 MB (Z hi)
__device__ __nv_bfloat16 g_zl[(size_t)NN * KZ];        // 83 MB (Z lo)
__device__ __nv_bfloat16 g_vh[HD * KZ];
__device__ __nv_bfloat16 g_vl[HD * KZ];
__device__ float g_h[NN * HD];
__device__ float g_m[NN * HD];
__device__ float g_hx[NN * (HD + NNF)];
__device__ float g_h2[NN * IC];
__device__ float g_eatt[NN];
__device__ float g_qstar[BG * 2 * IC];
__device__ float g_h0[BG * IC];
__device__ float g_c0[BG * IC];
__device__ float g_h1[BG * IC];
__device__ float g_c1[BG * IC];
__device__ float g_wcat0[512 * 384];
__device__ float g_wcat1[512 * 256];
__device__ float g_bs0[512];
__device__ float g_bs1[512];
__device__ float g_t2a[BG * 512];
__device__ int   g_gs[BG];
__device__ int   g_ge[BG];
// edge sort-by-dst
__device__ int   g_cnt[NN];
__device__ int   g_cur[NN];
__device__ int   g_offs[NN + 1];
__device__ int   g_eord[NE];

#define ID_E1     0
#define ID_H      1
#define ID_M      2
#define ID_HX     3
#define ID_H2     4
#define ID_QSTAR  5
#define ID_T2A    6
#define N_IDS     7

__device__ float* g_table[N_IDS];

__global__ void setup_ptrs_kernel() {
    g_table[ID_E1] = g_e1;
    g_table[ID_H] = g_h;   g_table[ID_M] = g_m;
    g_table[ID_HX] = g_hx; g_table[ID_H2] = g_h2;
    g_table[ID_QSTAR] = g_qstar;
    g_table[ID_T2A] = g_t2a;
}

__device__ __forceinline__ float sigf(float x) { return 1.0f / (1.0f + expf(-x)); }

// ---------------- bf16 mma helpers ----------------
__device__ __forceinline__ void mma_bf16(float* d, const unsigned* a, const unsigned* b) {
    asm volatile(
        "mma.sync.aligned.m16n8k16.row.col.f32.bf16.bf16.f32 "
        "{%0,%1,%2,%3}, {%4,%5,%6,%7}, {%8,%9}, {%0,%1,%2,%3};\n"
        : "+f"(d[0]), "+f"(d[1]), "+f"(d[2]), "+f"(d[3])
        : "r"(a[0]), "r"(a[1]), "r"(a[2]), "r"(a[3]), "r"(b[0]), "r"(b[1]));
}

__device__ __forceinline__ void split2_pack(float x0, float x1, unsigned& hi, unsigned& lo) {
    __nv_bfloat16 h0 = __float2bfloat16_rn(x0);
    __nv_bfloat16 h1 = __float2bfloat16_rn(x1);
    float r0 = x0 - __bfloat162float(h0);
    float r1 = x1 - __bfloat162float(h1);
    __nv_bfloat16 l0 = __float2bfloat16_rn(r0);
    __nv_bfloat16 l1 = __float2bfloat16_rn(r1);
    hi = (unsigned)__bfloat16_as_ushort(h0) | ((unsigned)__bfloat16_as_ushort(h1) << 16);
    lo = (unsigned)__bfloat16_as_ushort(l0) | ((unsigned)__bfloat16_as_ushort(l1) << 16);
}

// ---------------- bf16 3-pass tensor zgemm: g_m[NN,64] += Zcat @ Vcat^T (pre-split inputs)
#define APAD 40   // 80B rows: 16B-aligned, conflict-free frag LDS
__global__ __launch_bounds__(256) void zgemm_bf16_kernel(int ksplit)
{
    __shared__ __nv_bfloat16 Ah[128][APAD];
    __shared__ __nv_bfloat16 Al[128][APAD];
    __shared__ __nv_bfloat16 Bh[64][APAD];
    __shared__ __nv_bfloat16 Bl[64][APAD];

    const int tid = threadIdx.x;
    const int warp = tid >> 5, lane = tid & 31;
    const int m0 = blockIdx.y * 128;
    const int NCH = KZ / 32;
    const int c0 = (NCH * blockIdx.z) / ksplit;
    const int c1 = (NCH * (blockIdx.z + 1)) / ksplit;

    const int wm = (warp & 3) * 32;
    const int wn = (warp >> 2) * 32;
    const int g = lane >> 2, cc = lane & 3;

    const int arow = tid >> 1;            // 0..127
    const int apart = (tid & 1) * 16;     // 16 elems
    const int brow = tid >> 2;            // 0..63
    const int bpart = (tid & 3) * 8;      // 8 elems

    float acc[2][4][4];
#pragma unroll
    for (int mt = 0; mt < 2; mt++)
#pragma unroll
        for (int nt = 0; nt < 4; nt++)
#pragma unroll
            for (int r = 0; r < 4; r++) acc[mt][nt][r] = 0.0f;

    const int agrow = m0 + arow;
    const bool aval = (agrow < NN);
    const __nv_bfloat16* __restrict__ Azh = &g_zh[(size_t)(aval ? agrow : 0) * KZ];
    const __nv_bfloat16* __restrict__ Azl = &g_zl[(size_t)(aval ? agrow : 0) * KZ];
    const __nv_bfloat16* __restrict__ Bvh = &g_vh[(size_t)brow * KZ];
    const __nv_bfloat16* __restrict__ Bvl = &g_vl[(size_t)brow * KZ];
    const int4 z4 = make_int4(0, 0, 0, 0);

    for (int ch = c0; ch < c1; ch++) {
        int kk = ch * 32;
        {
            int4 h0 = aval ? *reinterpret_cast<const int4*>(&Azh[kk + apart])     : z4;
            int4 h1 = aval ? *reinterpret_cast<const int4*>(&Azh[kk + apart + 8]) : z4;
            int4 l0 = aval ? *reinterpret_cast<const int4*>(&Azl[kk + apart])     : z4;
            int4 l1 = aval ? *reinterpret_cast<const int4*>(&Azl[kk + apart + 8]) : z4;
            *reinterpret_cast<int4*>(&Ah[arow][apart])     = h0;
            *reinterpret_cast<int4*>(&Ah[arow][apart + 8]) = h1;
            *reinterpret_cast<int4*>(&Al[arow][apart])     = l0;
            *reinterpret_cast<int4*>(&Al[arow][apart + 8]) = l1;
        }
        {
            int4 h0 = *reinterpret_cast<const int4*>(&Bvh[kk + bpart]);
            int4 l0 = *reinterpret_cast<const int4*>(&Bvl[kk + bpart]);
            *reinterpret_cast<int4*>(&Bh[brow][bpart]) = h0;
            *reinterpret_cast<int4*>(&Bl[brow][bpart]) = l0;
        }
        __syncthreads();

#pragma unroll
        for (int ks = 0; ks < 2; ks++) {
            int kb = ks * 16;
            unsigned ah[2][4], al[2][4];
#pragma unroll
            for (int mt = 0; mt < 2; mt++) {
                int rb = wm + mt * 16 + g;
                ah[mt][0] = *reinterpret_cast<unsigned*>(&Ah[rb][kb + 2 * cc]);
                ah[mt][1] = *reinterpret_cast<unsigned*>(&Ah[rb + 8][kb + 2 * cc]);
                ah[mt][2] = *reinterpret_cast<unsigned*>(&Ah[rb][kb + 2 * cc + 8]);
                ah[mt][3] = *reinterpret_cast<unsigned*>(&Ah[rb + 8][kb + 2 * cc + 8]);
                al[mt][0] = *reinterpret_cast<unsigned*>(&Al[rb][kb + 2 * cc]);
                al[mt][1] = *reinterpret_cast<unsigned*>(&Al[rb + 8][kb + 2 * cc]);
                al[mt][2] = *reinterpret_cast<unsigned*>(&Al[rb][kb + 2 * cc + 8]);
                al[mt][3] = *reinterpret_cast<unsigned*>(&Al[rb + 8][kb + 2 * cc + 8]);
            }
            unsigned bh[4][2], bl[4][2];
#pragma unroll
            for (int nt = 0; nt < 4; nt++) {
                int nr = wn + nt * 8 + g;
                bh[nt][0] = *reinterpret_cast<unsigned*>(&Bh[nr][kb + 2 * cc]);
                bh[nt][1] = *reinterpret_cast<unsigned*>(&Bh[nr][kb + 2 * cc + 8]);
                bl[nt][0] = *reinterpret_cast<unsigned*>(&Bl[nr][kb + 2 * cc]);
                bl[nt][1] = *reinterpret_cast<unsigned*>(&Bl[nr][kb + 2 * cc + 8]);
            }
#pragma unroll
            for (int mt = 0; mt < 2; mt++)
#pragma unroll
                for (int nt = 0; nt < 4; nt++) {
                    mma_bf16(acc[mt][nt], ah[mt], bh[nt]);
                    mma_bf16(acc[mt][nt], ah[mt], bl[nt]);
                    mma_bf16(acc[mt][nt], al[mt], bh[nt]);
                }
        }
        __syncthreads();
    }

#pragma unroll
    for (int mt = 0; mt < 2; mt++) {
#pragma unroll
        for (int nt = 0; nt < 4; nt++) {
            int col = wn + nt * 8 + 2 * cc;
#pragma unroll
            for (int rr = 0; rr < 2; rr++) {
                int row = m0 + wm + mt * 16 + g + rr * 8;
                if (row >= NN) continue;
                atomicAdd(&g_m[(size_t)row * 64 + col],     acc[mt][nt][rr * 2 + 0]);
                atomicAdd(&g_m[(size_t)row * 64 + col + 1], acc[mt][nt][rr * 2 + 1]);
            }
        }
    }
}

// ---------------- fused GRU: gi = m@wih^T, gh = h@whh^T, pointwise -> h (in place)
__global__ __launch_bounds__(256) void gru_fused_kernel(
    const float* __restrict__ wih, const float* __restrict__ whh,
    const float* __restrict__ bih, const float* __restrict__ bhh)
{
    __shared__ float s_am[16][33];
    __shared__ float s_ah[16][33];
    __shared__ float s_bi[16][200];
    __shared__ float s_bh[16][200];

    const int tid = threadIdx.x;
    const int tx = tid & 15, ty = tid >> 4;   // c0 = tx*4, rows 2*ty..+1
    const int r0 = blockIdx.x * 32;

    float ai[2][3][4], ah[2][3][4];
#pragma unroll
    for (int r = 0; r < 2; r++)
#pragma unroll
        for (int gg = 0; gg < 3; gg++)
#pragma unroll
            for (int j = 0; j < 4; j++) { ai[r][gg][j] = 0.0f; ah[r][gg][j] = 0.0f; }

    for (int kk = 0; kk < 64; kk += 16) {
#pragma unroll
        for (int j = 0; j < 2; j++) {
            int idx = tid * 2 + j;
            int row = idx >> 4, k = idx & 15;
            int gr = r0 + row;
            s_am[k][row] = (gr < NN) ? g_m[gr * 64 + kk + k] : 0.0f;
            s_ah[k][row] = (gr < NN) ? g_h[gr * 64 + kk + k] : 0.0f;
        }
#pragma unroll
        for (int j = 0; j < 12; j++) {
            int idx = tid * 12 + j;
            int col = idx >> 4, k = idx & 15;
            s_bi[k][col] = wih[col * 64 + kk + k];
            s_bh[k][col] = whh[col * 64 + kk + k];
        }
        __syncthreads();

#pragma unroll
        for (int k = 0; k < 16; k++) {
            float am[2], ahv[2];
#pragma unroll
            for (int r = 0; r < 2; r++) { am[r] = s_am[k][2 * ty + r]; ahv[r] = s_ah[k][2 * ty + r]; }
#pragma unroll
            for (int gg = 0; gg < 3; gg++)
#pragma unroll
                for (int j = 0; j < 4; j++) {
                    float bi = s_bi[k][gg * 64 + tx * 4 + j];
                    float bh = s_bh[k][gg * 64 + tx * 4 + j];
#pragma unroll
                    for (int r = 0; r < 2; r++) {
                        ai[r][gg][j] = fmaf(am[r], bi, ai[r][gg][j]);
                        ah[r][gg][j] = fmaf(ahv[r], bh, ah[r][gg][j]);
                    }
                }
        }
        __syncthreads();
    }

#pragma unroll
    for (int r = 0; r < 2; r++) {
        int gr = r0 + 2 * ty + r;
        if (gr >= NN) continue;
#pragma unroll
        for (int j = 0; j < 4; j++) {
            int c = tx * 4 + j;
            float grv = ai[r][0][j] + bih[c]       + ah[r][0][j] + bhh[c];
            float gzv = ai[r][1][j] + bih[64 + c]  + ah[r][1][j] + bhh[64 + c];
            float ginn = ai[r][2][j] + bih[128 + c];
            float ghnn = ah[r][2][j] + bhh[128 + c];
            float rr = sigf(grv);
            float zz = sigf(gzv);
            float nn = tanhf(ginn + rr * ghnn);
            float hold = g_h[gr * 64 + c];
            g_h[gr * 64 + c] = (1.0f - zz) * nn + zz * hold;
        }
    }
}

// ---------------- fused Set2Set LSTM step ----------------
// mode 0: input [qstar|h0] K=384, W=g_wcat0, bs=g_bs0, state (h0,c0)
// mode 1: input [h0|h1]    K=256, W=g_wcat1, bs=g_bs1, state (h1,c1)
__global__ __launch_bounds__(256) void lstm_step_kernel(int mode)
{
    __shared__ float s_a[16][33];
    __shared__ float s_b[16][516];

    const int K = mode ? 256 : 384;
    const float* __restrict__ W  = mode ? g_wcat1 : g_wcat0;
    const float* __restrict__ bs = mode ? g_bs1 : g_bs0;
    float* __restrict__ hS = mode ? g_h1 : g_h0;
    float* __restrict__ cS = mode ? g_c1 : g_c0;

    const int tid = threadIdx.x;
    const int tx = tid & 31, ty = tid >> 5;   // c0 = tx*4 (0..124), rows ty*4..+3
    const int r0 = blockIdx.x * 32;

    float acc[4][4][4];
#pragma unroll
    for (int r = 0; r < 4; r++)
#pragma unroll
        for (int gg = 0; gg < 4; gg++)
#pragma unroll
            for (int j = 0; j < 4; j++) acc[r][gg][j] = 0.0f;

    for (int kk = 0; kk < K; kk += 16) {
#pragma unroll
        for (int j = 0; j < 2; j++) {
            int idx = tid * 2 + j;
            int row = idx >> 4, k = idx & 15;
            int gb = r0 + row;
            int col = kk + k;
            float v;
            if (mode == 0) v = (col < 256) ? g_qstar[gb * 256 + col] : g_h0[gb * 128 + col - 256];
            else           v = (col < 128) ? g_h0[gb * 128 + col]    : g_h1[gb * 128 + col - 128];
            s_a[k][row] = v;
        }
#pragma unroll
        for (int j = 0; j < 32; j++) {
            int idx = tid * 32 + j;
            int col = idx >> 4, k = idx & 15;
            s_b[k][col] = W[col * K + kk + k];
        }
        __syncthreads();

#pragma unroll
        for (int k = 0; k < 16; k++) {
            float a[4];
#pragma unroll
            for (int r = 0; r < 4; r++) a[r] = s_a[k][ty * 4 + r];
#pragma unroll
            for (int gg = 0; gg < 4; gg++)
#pragma unroll
                for (int j = 0; j < 4; j++) {
                    float b = s_b[k][gg * 128 + tx * 4 + j];
#pragma unroll
                    for (int r = 0; r < 4; r++)
                        acc[r][gg][j] = fmaf(a[r], b, acc[r][gg][j]);
                }
        }
        __syncthreads();
    }

#pragma unroll
    for (int r = 0; r < 4; r++) {
        int gb = r0 + ty * 4 + r;
#pragma unroll
        for (int j = 0; j < 4; j++) {
            int c = tx * 4 + j;
            float gi = acc[r][0][j] + bs[c];
            float gf = acc[r][1][j] + bs[128 + c];
            float gg = acc[r][2][j] + bs[256 + c];
            float go = acc[r][3][j] + bs[384 + c];
            float cold = cS[gb * 128 + c];
            float cn = sigf(gf) * cold + sigf(gi) * tanhf(gg);
            cS[gb * 128 + c] = cn;
            hS[gb * 128 + c] = sigf(go) * tanhf(cn);
        }
    }
}

// ---------------- fused attention (dot + softmax + weighted sum + q_star) ----------------
__global__ void attn_fused_kernel()
{
    __shared__ float q[128];
    __shared__ float red[128];
    int b = blockIdx.x;
    int tid = threadIdx.x;
    int s = g_gs[b], e = g_ge[b];

    q[tid] = g_h1[b * 128 + tid];
    __syncthreads();

    int warp = tid >> 5, lane = tid & 31;
    for (int n = s + warp; n < e; n += 4) {
        const float* hr = &g_h2[(size_t)n * 128];
        float sum = hr[lane] * q[lane] + hr[lane + 32] * q[lane + 32]
                  + hr[lane + 64] * q[lane + 64] + hr[lane + 96] * q[lane + 96];
#pragma unroll
        for (int o = 16; o > 0; o >>= 1) sum += __shfl_xor_sync(0xffffffffu, sum, o);
        if (lane == 0) g_eatt[n] = sum;
    }
    __syncthreads();

    float mx = -1e30f;
    for (int n = s + tid; n < e; n += 128) mx = fmaxf(mx, g_eatt[n]);
    red[tid] = mx;
    __syncthreads();
    for (int o = 64; o > 0; o >>= 1) {
        if (tid < o) red[tid] = fmaxf(red[tid], red[tid + o]);
        __syncthreads();
    }
    float m = red[0];

    float rd = 0.0f, den = 0.0f;
    for (int n = s; n < e; n++) {
        float a = expf(g_eatt[n] - m);
        den += a;
        rd = fmaf(a, g_h2[(size_t)n * IC + tid], rd);
    }
    g_qstar[b * 256 + 128 + tid] = (den > 0.0f) ? (rd / den) : 0.0f;
    g_qstar[b * 256 + tid] = q[tid];
}

// ---------------- generic tiled SGEMM (lin, output MLP) ----------------
template <int BM, int BN, int BK, int TM, int TN, int THREADS, bool RELU>
__global__ __launch_bounds__(THREADS) void sgemm_kernel(
    int a_id, const float* a_ext,
    int b_id, const float* b_ext,
    const float* bias,
    int c_id, float* c_ext,
    int M, int N, int K)
{
    const float* __restrict__ A  = (a_id >= 0) ? g_table[a_id] : a_ext;
    const float* __restrict__ Bw = (b_id >= 0) ? g_table[b_id] : b_ext;
    float* __restrict__ C = (c_id >= 0) ? g_table[c_id] : c_ext;

    __shared__ float As[BK][BM + 4];
    __shared__ float Bs[BK][BN + 4];

    const int tid = threadIdx.x;
    const int m0 = blockIdx.y * BM;
    const int n0 = blockIdx.x * BN;
    const int NTX = BN / TN;
    const int tx = tid % NTX;
    const int ty = tid / NTX;

    float acc[TM][TN];
#pragma unroll
    for (int i = 0; i < TM; i++)
#pragma unroll
        for (int j = 0; j < TN; j++) acc[i][j] = 0.0f;

    for (int kk = 0; kk < K; kk += BK) {
#pragma unroll
        for (int idx = tid; idx < BM * BK; idx += THREADS) {
            int mm = idx / BK, k = idx % BK;
            int row = m0 + mm, col = kk + k;
            As[k][mm] = (row < M && col < K) ? A[(size_t)row * K + col] : 0.0f;
        }
#pragma unroll
        for (int idx = tid; idx < BN * BK; idx += THREADS) {
            int nn2 = idx / BK, k = idx % BK;
            int row = n0 + nn2, col = kk + k;
            Bs[k][nn2] = (row < N && col < K) ? Bw[(size_t)row * K + col] : 0.0f;
        }
        __syncthreads();

#pragma unroll
        for (int k = 0; k < BK; k++) {
            float a[TM], b[TN];
#pragma unroll
            for (int i = 0; i < TM; i++) a[i] = As[k][ty * TM + i];
#pragma unroll
            for (int j = 0; j < TN; j++) b[j] = Bs[k][tx * TN + j];
#pragma unroll
            for (int i = 0; i < TM; i++)
#pragma unroll
                for (int j = 0; j < TN; j++) acc[i][j] = fmaf(a[i], b[j], acc[i][j]);
        }
        __syncthreads();
    }

#pragma unroll
    for (int i = 0; i < TM; i++) {
        int row = m0 + ty * TM + i;
        if (row >= M) continue;
#pragma unroll
        for (int j = 0; j < TN; j++) {
            int col = n0 + tx * TN + j;
            if (col >= N) continue;
            float v = acc[i][j] + (bias ? bias[col] : 0.0f);
            if (RELU) v = fmaxf(v, 0.0f);
            C[(size_t)row * N + col] = v;
        }
    }
}

// ---------------- edge sort-by-dst ----------------
__global__ void hist_zero_kernel() {
    int i = blockIdx.x * blockDim.x + threadIdx.x;
    if (i < NN) { g_cnt[i] = 0; g_cur[i] = 0; }
    if (i < BG) { g_gs[i] = NN; g_ge[i] = 0; }
}
__global__ void hist_kernel(const int* __restrict__ dst) {
    int e = blockIdx.x * blockDim.x + threadIdx.x;
    if (e >= NE) return;
    int d = dst[e];
    if ((unsigned)d < NN) atomicAdd(&g_cnt[d], 1);
}
__global__ void scan_kernel() {
    __shared__ int sh[1024];
    __shared__ int carry;
    int tid = threadIdx.x;
    if (tid == 0) carry = 0;
    __syncthreads();
    for (int base = 0; base < NN; base += 1024) {
        int i = base + tid;
        int v = (i < NN) ? g_cnt[i] : 0;
        sh[tid] = v;
        __syncthreads();
        for (int off = 1; off < 1024; off <<= 1) {
            int t = (tid >= off) ? sh[tid - off] : 0;
            __syncthreads();
            sh[tid] += t;
            __syncthreads();
        }
        int c0 = carry;
        int myoff = c0 + sh[tid] - v;
        __syncthreads();
        if (tid == 1023) carry = c0 + sh[1023];
        __syncthreads();
        if (i < NN) g_offs[i] = myoff;
    }
    if (tid == 0) g_offs[NN] = carry;
}
__global__ void scatter_kernel(const int* __restrict__ dst) {
    int e = blockIdx.x * blockDim.x + threadIdx.x;
    if (e >= NE) return;
    int d = dst[e];
    if ((unsigned)d >= NN) return;
    int p = g_offs[d] + atomicAdd(&g_cur[d], 1);
    g_eord[p] = e;
}

// ---------------- Z accumulate (writes pre-split bf16 hi/lo) ----------------
__global__ __launch_bounds__(256) void zacc_kernel(const int* __restrict__ src) {
    __shared__ float sh[4][64];
    __shared__ float se[4][64];
    int d = blockIdx.x;
    int beg = g_offs[d], end = g_offs[d + 1];
    int tid = threadIdx.x;
    int i0 = (tid >> 4) << 2;
    int k0 = (tid & 15) << 2;
    float acc[4][4];
#pragma unroll
    for (int r = 0; r < 4; r++)
#pragma unroll
        for (int c = 0; c < 4; c++) acc[r][c] = 0.0f;
    float hs = 0.0f;

    int j = tid >> 6, l = tid & 63;
    for (int p = beg; p < end; p += 4) {
        int nv = end - p;
        if (j < nv) {
            int e = g_eord[p + j];
            int s = src[e];
            sh[j][l] = ((unsigned)s < NN) ? g_h[s * 64 + l] : 0.0f;
            se[j][l] = g_e1[e * 64 + l];
        } else { sh[j][l] = 0.0f; se[j][l] = 0.0f; }
        __syncthreads();
#pragma unroll
        for (int j2 = 0; j2 < 4; j2++) {
            float4 hv = *reinterpret_cast<float4*>(&sh[j2][i0]);
            float4 ev = *reinterpret_cast<float4*>(&se[j2][k0]);
            acc[0][0] = fmaf(hv.x, ev.x, acc[0][0]); acc[0][1] = fmaf(hv.x, ev.y, acc[0][1]);
            acc[0][2] = fmaf(hv.x, ev.z, acc[0][2]); acc[0][3] = fmaf(hv.x, ev.w, acc[0][3]);
            acc[1][0] = fmaf(hv.y, ev.x, acc[1][0]); acc[1][1] = fmaf(hv.y, ev.y, acc[1][1]);
            acc[1][2] = fmaf(hv.y, ev.z, acc[1][2]); acc[1][3] = fmaf(hv.y, ev.w, acc[1][3]);
            acc[2][0] = fmaf(hv.z, ev.x, acc[2][0]); acc[2][1] = fmaf(hv.z, ev.y, acc[2][1]);
            acc[2][2] = fmaf(hv.z, ev.z, acc[2][2]); acc[2][3] = fmaf(hv.z, ev.w, acc[2][3]);
            acc[3][0] = fmaf(hv.w, ev.x, acc[3][0]); acc[3][1] = fmaf(hv.w, ev.y, acc[3][1]);
            acc[3][2] = fmaf(hv.w, ev.z, acc[3][2]); acc[3][3] = fmaf(hv.w, ev.w, acc[3][3]);
        }
        if (tid < 64) hs += sh[0][tid] + sh[1][tid] + sh[2][tid] + sh[3][tid];
        __syncthreads();
    }

    size_t rowbase = (size_t)d * KZ;
#pragma unroll
    for (int r = 0; r < 4; r++) {
        unsigned h0, l0, h1, l1;
        split2_pack(acc[r][0], acc[r][1], h0, l0);
        split2_pack(acc[r][2], acc[r][3], h1, l1);
        size_t off = rowbase + (size_t)(i0 + r) * 64 + k0;
        *reinterpret_cast<unsigned*>(&g_zh[off])     = h0;
        *reinterpret_cast<unsigned*>(&g_zh[off + 2]) = h1;
        *reinterpret_cast<unsigned*>(&g_zl[off])     = l0;
        *reinterpret_cast<unsigned*>(&g_zl[off + 2]) = l1;
    }
    if (tid < 64) {
        __nv_bfloat16 hb = __float2bfloat16_rn(hs);
        float rres = hs - __bfloat162float(hb);
        g_zh[rowbase + 4096 + tid] = hb;
        g_zl[rowbase + 4096 + tid] = __float2bfloat16_rn(rres);
    }
}

// ---------------- weight repacks ----------------
__global__ void prep_vcat_kernel(const float* __restrict__ w1c, const float* __restrict__ b1c) {
    int idx = blockIdx.x * blockDim.x + threadIdx.x;
    if (idx >= HD * KZ) return;
    int o = idx / KZ, c = idx % KZ;
    float v;
    if (c < 4096) {
        int i = c >> 6, k = c & 63;
        v = w1c[(i * 64 + o) * 64 + k];
    } else {
        v = b1c[(c - 4096) * 64 + o];
    }
    __nv_bfloat16 hb = __float2bfloat16_rn(v);
    g_vh[idx] = hb;
    g_vl[idx] = __float2bfloat16_rn(v - __bfloat162float(hb));
}

// ---------------- small kernels ----------------
__global__ void zero_m_kernel() {
    int i = blockIdx.x * blockDim.x + threadIdx.x;
    if (i < NN * HD) g_m[i] = 0.0f;
}
__global__ void zero_s2s_kernel() {
    int i = blockIdx.x * blockDim.x + threadIdx.x;
    if (i < BG * 256) g_qstar[i] = 0.0f;
    if (i < BG * IC) { g_h0[i] = 0.0f; g_c0[i] = 0.0f; g_h1[i] = 0.0f; g_c1[i] = 0.0f; }
}

__global__ void init_h_kernel(const float* __restrict__ x) {
    int idx = blockIdx.x * blockDim.x + threadIdx.x;
    if (idx >= NN * HD) return;
    int n = idx / HD, c = idx % HD;
    g_h[idx] = (c < NNF) ? x[n * NNF + c] : 0.0f;
}

__global__ void edge_mlp_kernel(const float* __restrict__ ea,
                                const float* __restrict__ w1a, const float* __restrict__ b1a,
                                const float* __restrict__ w1b, const float* __restrict__ b1b)
{
    __shared__ float wa[NEF][HD];
    __shared__ float wb[HD][HD];
    __shared__ float ba[HD], bb[HD];
    __shared__ float s1[4][HD];

    int tid = threadIdx.x;
    for (int i = tid; i < HD * NEF; i += blockDim.x) { int k = i / NEF, f = i % NEF; wa[f][k] = w1a[i]; }
    for (int i = tid; i < HD * HD; i += blockDim.x)  { int k = i / HD,  j = i % HD;  wb[j][k] = w1b[i]; }
    if (tid < HD) { ba[tid] = b1a[tid]; bb[tid] = b1b[tid]; }
    __syncthreads();

    int le = tid >> 6;
    int k  = tid & 63;
    for (int base = blockIdx.x * 4; base < NE; base += gridDim.x * 4) {
        int e = base + le;
        float t1 = ba[k];
#pragma unroll
        for (int f = 0; f < NEF; f++) t1 = fmaf(ea[e * NEF + f], wa[f][k], t1);
        s1[le][k] = fmaxf(t1, 0.0f);
        __syncthreads();
        float t2 = bb[k];
#pragma unroll
        for (int j = 0; j < HD; j++) t2 = fmaf(s1[le][j], wb[j][k], t2);
        g_e1[e * HD + k] = fmaxf(t2, 0.0f);
        __syncthreads();
    }
}

__global__ void concat_hx_kernel(const float* __restrict__ x)
{
    int idx = blockIdx.x * blockDim.x + threadIdx.x;
    const int W = HD + NNF;
    if (idx >= NN * W) return;
    int n = idx / W, c = idx % W;
    g_hx[idx] = (c < HD) ? g_h[n * HD + c] : x[n * NNF + (c - HD)];
}

__global__ void prep_lstm_kernel(const float* __restrict__ wih0, const float* __restrict__ whh0,
                                 const float* __restrict__ bih0, const float* __restrict__ bhh0,
                                 const float* __restrict__ wih1, const float* __restrict__ whh1,
                                 const float* __restrict__ bih1, const float* __restrict__ bhh1)
{
    int i = blockIdx.x * blockDim.x + threadIdx.x;
    const int n0 = 512 * 384, n1 = 512 * 256;
    if (i < n0) {
        int j = i / 384, c = i % 384;
        g_wcat0[i] = (c < 256) ? wih0[j * 256 + c] : whh0[j * 128 + (c - 256)];
    } else if (i < n0 + n1) {
        int k = i - n0; int j = k / 256, c = k % 256;
        g_wcat1[k] = (c < 128) ? wih1[j * 128 + c] : whh1[j * 128 + (c - 128)];
    } else if (i < n0 + n1 + 512) {
        int j = i - n0 - n1; g_bs0[j] = bih0[j] + bhh0[j];
    } else if (i < n0 + n1 + 1024) {
        int j = i - n0 - n1 - 512; g_bs1[j] = bih1[j] + bhh1[j];
    }
}

__global__ void seg_mark_kernel(const int* __restrict__ batch) {
    int n = blockIdx.x * blockDim.x + threadIdx.x;
    if (n >= NN) return;
    int b = batch[n];
    if ((unsigned)b >= BG) return;
    atomicMin(&g_gs[b], n);
    atomicMax(&g_ge[b], n + 1);
}

// ---------------- host orchestration ----------------
extern "C" void kernel_launch(void* const* d_in, const int* in_sizes, int n_in,
                              void* d_out, int out_size)
{
    const float *x = 0, *ea = 0, *w1a = 0, *b1a = 0, *w1b = 0, *b1b = 0, *w1c = 0, *b1c = 0;
    const float *gwih = 0, *gwhh = 0, *gbih = 0, *gbhh = 0, *linw = 0, *linb = 0;
    const float *lwih0 = 0, *lwhh0 = 0, *lbih0 = 0, *lbhh0 = 0;
    const float *lwih1 = 0, *lwhh1 = 0, *lbih1 = 0, *lbhh1 = 0;
    const float *w2a = 0, *b2a = 0, *w2b = 0, *b2b = 0;
    const int *eidx = 0, *batch = 0;

    int c64 = 0, c4096 = 0, c12288 = 0, c192 = 0, c131072 = 0, c65536 = 0, c512 = 0;
    for (int i = 0; i < n_in; i++) {
        const void* p = d_in[i];
        int s = in_sizes[i];
        if      (s == 110000) x = (const float*)p;
        else if (s == 200000) ea = (const float*)p;
        else if (s == 100000) eidx = (const int*)p;
        else if (s == 10000)  batch = (const int*)p;
        else if (s == 1)      { }
        else if (s == 256)    w1a = (const float*)p;
        else if (s == 64)     { if (c64++ == 0) b1a = (const float*)p; else b1b = (const float*)p; }
        else if (s == 4096)   { if (c4096++ == 0) w1b = (const float*)p; else b1c = (const float*)p; }
        else if (s == 262144) w1c = (const float*)p;
        else if (s == 12288)  { if (c12288++ == 0) gwih = (const float*)p; else gwhh = (const float*)p; }
        else if (s == 192)    { if (c192++ == 0) gbih = (const float*)p; else gbhh = (const float*)p; }
        else if (s == 9600)   linw = (const float*)p;
        else if (s == 128)    linb = (const float*)p;
        else if (s == 131072) { if (c131072++ == 0) lwih0 = (const float*)p; else w2a = (const float*)p; }
        else if (s == 65536)  { int k = c65536++; if (k == 0) lwhh0 = (const float*)p;
                                else if (k == 1) lwih1 = (const float*)p; else lwhh1 = (const float*)p; }
        else if (s == 512)    { int k = c512++;
                                if (k == 0) lbih0 = (const float*)p;
                                else if (k == 1) lbhh0 = (const float*)p;
                                else if (k == 2) lbih1 = (const float*)p;
                                else if (k == 3) lbhh1 = (const float*)p;
                                else b2a = (const float*)p; }
        else if (s == 6144)   w2b = (const float*)p;
        else if (s == 12)     b2b = (const float*)p;
    }
    float* out = (float*)d_out;
    const int* src = eidx;
    const int* dst = eidx + NE;

    setup_ptrs_kernel<<<1, 1>>>();

    // h init + edge MLP + Vcat repack (pre-split bf16)
    init_h_kernel<<<(NN * HD + 255) / 256, 256>>>(x);
    edge_mlp_kernel<<<256, 256>>>(ea, w1a, b1a, w1b, b1b);
    prep_vcat_kernel<<<(HD * KZ + 255) / 256, 256>>>(w1c, b1c);

    // sort edges by dst (+ seg init folded into hist_zero)
    hist_zero_kernel<<<(NN + 255) / 256, 256>>>();
    hist_kernel<<<(NE + 255) / 256, 256>>>(dst);
    scan_kernel<<<1, 1024>>>();
    scatter_kernel<<<(NE + 255) / 256, 256>>>(dst);

    // set2set prep
    prep_lstm_kernel<<<(512 * 384 + 512 * 256 + 1024 + 255) / 256, 256>>>(
        lwih0, lwhh0, lbih0, lbhh0, lwih1, lwhh1, lbih1, lbhh1);
    seg_mark_kernel<<<(NN + 255) / 256, 256>>>(batch);

    const int MB128 = (NN + 127) / 128;   // 79

    // T message-passing steps
    for (int t = 0; t < 3; t++) {
        zacc_kernel<<<NN, 256>>>(src);
        zero_m_kernel<<<(NN * HD + 255) / 256, 256>>>();
        {
            dim3 grid(1, MB128, 2);
            zgemm_bf16_kernel<<<grid, 256>>>(2);
        }
        gru_fused_kernel<<<(NN + 31) / 32, 256>>>(gwih, gwhh, gbih, gbhh);
    }

    // lin: h2 = [h|x] @ lin_w^T + lin_b  (K=75)
    concat_hx_kernel<<<(NN * (HD + NNF) + 255) / 256, 256>>>(x);
    {
        dim3 grid((IC + 63) / 64, (NN + 63) / 64);
        sgemm_kernel<64, 64, 16, 4, 4, 256, false><<<grid, 256>>>(
            ID_HX, nullptr, -1, linw, linb, ID_H2, nullptr, NN, IC, HD + NNF);
    }

    // Set2Set (fused)
    zero_s2s_kernel<<<(BG * 256 + 255) / 256, 256>>>();
    for (int ms = 0; ms < 3; ms++) {
        lstm_step_kernel<<<BG / 32, 256>>>(0);
        lstm_step_kernel<<<BG / 32, 256>>>(1);
        attn_fused_kernel<<<BG, 128>>>();
    }

    // output MLP
    {
        dim3 grid1((512 + 63) / 64, (BG + 31) / 32);
        sgemm_kernel<32, 64, 16, 2, 4, 256, true><<<grid1, 256>>>(
            ID_QSTAR, nullptr, -1, w2a, b2a, ID_T2A, nullptr, BG, 512, 256);
        dim3 grid2(1, (BG + 31) / 32);
        sgemm_kernel<32, 64, 16, 2, 4, 256, false><<<grid2, 256>>>(
            ID_T2A, nullptr, -1, w2b, b2b, -1, out, BG, NTG, 512);
    }
}

// round 9
// speedup vs baseline: 1.7370x; 1.7370x over previous
#include <cuda_runtime.h>
#include <cuda_bf16.h>
#include <math.h>
#include <stdint.h>

#define NN  10000   // nodes
#define NE  50000   // edges
#define HD  64      // hidden
#define BG  256     // batch graphs
#define NEF 4
#define NNF 11
#define NTG 12      // targets
#define IC  128     // 2H
#define KZ  4160    // 64*65 : Zcat columns (64i x 64k + 64 hsum)

// ---------------- scratch (static device globals; no allocation) ----------------
__device__ float g_e1[NE * HD];
__device__ float g_zcat[(size_t)NN * KZ];              // 166 MB
__device__ float g_vcat[HD * KZ];
__device__ float g_h[NN * HD];
__device__ float g_m[NN * HD];
__device__ float g_gi[NN * 3 * HD];
__device__ float g_gh[NN * 3 * HD];
__device__ float g_hx[NN * (HD + NNF)];
__device__ float g_h2[NN * IC];
__device__ float g_eatt[NN];
__device__ float g_qstar[BG * 2 * IC];
__device__ float g_h0[BG * IC];
__device__ float g_c0[BG * IC];
__device__ float g_h1[BG * IC];
__device__ float g_c1[BG * IC];
__device__ float g_lin0[BG * 384];
__device__ float g_lin1[BG * 256];
__device__ float g_gates[BG * 4 * IC];
__device__ float g_wcat0[512 * 384];
__device__ float g_wcat1[512 * 256];
__device__ float g_bs0[512];
__device__ float g_bs1[512];
__device__ float g_t2a[BG * 512];
__device__ int   g_gs[BG];
__device__ int   g_ge[BG];
// edge sort-by-dst
__device__ int   g_cnt[NN];
__device__ int   g_cur[NN];
__device__ int   g_offs[NN + 1];
__device__ int   g_eord[NE];

#define ID_E1     0
#define ID_H      1
#define ID_M      2
#define ID_GI     3
#define ID_GH     4
#define ID_HX     5
#define ID_H2     6
#define ID_QSTAR  7
#define ID_H0     8
#define ID_C0     9
#define ID_H1     10
#define ID_C1     11
#define ID_LIN0   12
#define ID_LIN1   13
#define ID_GATES  14
#define ID_WCAT0  15
#define ID_WCAT1  16
#define ID_BS0    17
#define ID_BS1    18
#define ID_T2A    19
#define N_IDS     20

__device__ float* g_table[N_IDS];

__global__ void setup_ptrs_kernel() {
    g_table[ID_E1] = g_e1;
    g_table[ID_H] = g_h;         g_table[ID_M] = g_m;
    g_table[ID_GI] = g_gi;       g_table[ID_GH] = g_gh;
    g_table[ID_HX] = g_hx;       g_table[ID_H2] = g_h2;
    g_table[ID_QSTAR] = g_qstar; g_table[ID_H0] = g_h0;
    g_table[ID_C0] = g_c0;       g_table[ID_H1] = g_h1;
    g_table[ID_C1] = g_c1;       g_table[ID_LIN0] = g_lin0;
    g_table[ID_LIN1] = g_lin1;   g_table[ID_GATES] = g_gates;
    g_table[ID_WCAT0] = g_wcat0; g_table[ID_WCAT1] = g_wcat1;
    g_table[ID_BS0] = g_bs0;     g_table[ID_BS1] = g_bs1;
    g_table[ID_T2A] = g_t2a;
}

__device__ __forceinline__ float sigf(float x) { return 1.0f / (1.0f + expf(-x)); }

// ---------------- bf16 mma helpers ----------------
__device__ __forceinline__ void mma_bf16(float* d, const unsigned* a, const unsigned* b) {
    asm volatile(
        "mma.sync.aligned.m16n8k16.row.col.f32.bf16.bf16.f32 "
        "{%0,%1,%2,%3}, {%4,%5,%6,%7}, {%8,%9}, {%0,%1,%2,%3};\n"
        : "+f"(d[0]), "+f"(d[1]), "+f"(d[2]), "+f"(d[3])
        : "r"(a[0]), "r"(a[1]), "r"(a[2]), "r"(a[3]), "r"(b[0]), "r"(b[1]));
}

__device__ __forceinline__ void split2_pack(float x0, float x1, unsigned& hi, unsigned& lo) {
    __nv_bfloat16 h0 = __float2bfloat16_rn(x0);
    __nv_bfloat16 h1 = __float2bfloat16_rn(x1);
    float r0 = x0 - __bfloat162float(h0);
    float r1 = x1 - __bfloat162float(h1);
    __nv_bfloat16 l0 = __float2bfloat16_rn(r0);
    __nv_bfloat16 l1 = __float2bfloat16_rn(r1);
    hi = (unsigned)__bfloat16_as_ushort(h0) | ((unsigned)__bfloat16_as_ushort(h1) << 16);
    lo = (unsigned)__bfloat16_as_ushort(l0) | ((unsigned)__bfloat16_as_ushort(l1) << 16);
}

// ---------------- bf16 3-pass tensor zgemm: g_m[NN,64] += Zcat[NN,KZ] @ Vcat[64,KZ]^T
// split-at-stage, register prefetch of next chunk, K-split with atomic epilogue.
#define APAD 40   // 80B rows: 16B-aligned, conflict-free frag LDS
__global__ __launch_bounds__(256, 2) void zgemm_bf16_kernel(int ksplit)
{
    __shared__ __nv_bfloat16 Ah[128][APAD];
    __shared__ __nv_bfloat16 Al[128][APAD];
    __shared__ __nv_bfloat16 Bh[64][APAD];
    __shared__ __nv_bfloat16 Bl[64][APAD];

    const int tid = threadIdx.x;
    const int warp = tid >> 5, lane = tid & 31;
    const int m0 = blockIdx.y * 128;
    const int NCH = KZ / 32;                  // 130 chunks of 32
    const int c0 = (NCH * blockIdx.z) / ksplit;
    const int c1 = (NCH * (blockIdx.z + 1)) / ksplit;

    const int wm = (warp & 3) * 32;           // 4 warps over M=128
    const int wn = (warp >> 2) * 32;          // 2 warps over N=64
    const int g = lane >> 2, cc = lane & 3;

    // loader decomposition
    const int arow = tid >> 1;                // 0..127
    const int acol = (tid & 1) * 16;          // 16 floats each
    const int brow = tid >> 2;                // 0..63
    const int bcol = (tid & 3) * 8;           // 8 floats each

    float acc[2][4][4];
#pragma unroll
    for (int mt = 0; mt < 2; mt++)
#pragma unroll
        for (int nt = 0; nt < 4; nt++)
#pragma unroll
            for (int r = 0; r < 4; r++) acc[mt][nt][r] = 0.0f;

    const int agrow = m0 + arow;
    const bool aval = (agrow < NN);
    const float* __restrict__ Asrc = &g_zcat[(size_t)(aval ? agrow : 0) * KZ];
    const float* __restrict__ Bsrc = &g_vcat[(size_t)brow * KZ];
    const float4 z4 = make_float4(0.f, 0.f, 0.f, 0.f);

    // prologue: prefetch chunk c0 into registers
    float4 pa[4], pb[2];
    {
        int kk = c0 * 32;
#pragma unroll
        for (int j = 0; j < 4; j++)
            pa[j] = aval ? *reinterpret_cast<const float4*>(Asrc + kk + acol + j * 4) : z4;
#pragma unroll
        for (int j = 0; j < 2; j++)
            pb[j] = *reinterpret_cast<const float4*>(Bsrc + kk + bcol + j * 4);
    }

    for (int ch = c0; ch < c1; ch++) {
        // stage registers -> smem with bf16 split
#pragma unroll
        for (int j = 0; j < 4; j++) {
            unsigned h0, l0, h1, l1;
            split2_pack(pa[j].x, pa[j].y, h0, l0);
            split2_pack(pa[j].z, pa[j].w, h1, l1);
            *reinterpret_cast<unsigned*>(&Ah[arow][acol + j * 4])     = h0;
            *reinterpret_cast<unsigned*>(&Ah[arow][acol + j * 4 + 2]) = h1;
            *reinterpret_cast<unsigned*>(&Al[arow][acol + j * 4])     = l0;
            *reinterpret_cast<unsigned*>(&Al[arow][acol + j * 4 + 2]) = l1;
        }
#pragma unroll
        for (int j = 0; j < 2; j++) {
            unsigned h0, l0, h1, l1;
            split2_pack(pb[j].x, pb[j].y, h0, l0);
            split2_pack(pb[j].z, pb[j].w, h1, l1);
            *reinterpret_cast<unsigned*>(&Bh[brow][bcol + j * 4])     = h0;
            *reinterpret_cast<unsigned*>(&Bh[brow][bcol + j * 4 + 2]) = h1;
            *reinterpret_cast<unsigned*>(&Bl[brow][bcol + j * 4])     = l0;
            *reinterpret_cast<unsigned*>(&Bl[brow][bcol + j * 4 + 2]) = l1;
        }
        __syncthreads();

        // prefetch next chunk (overlaps with the MMA block below)
        if (ch + 1 < c1) {
            int kk = (ch + 1) * 32;
#pragma unroll
            for (int j = 0; j < 4; j++)
                pa[j] = aval ? *reinterpret_cast<const float4*>(Asrc + kk + acol + j * 4) : z4;
#pragma unroll
            for (int j = 0; j < 2; j++)
                pb[j] = *reinterpret_cast<const float4*>(Bsrc + kk + bcol + j * 4);
        }

#pragma unroll
        for (int ks = 0; ks < 2; ks++) {
            int kb = ks * 16;
            unsigned ah[2][4], al[2][4];
#pragma unroll
            for (int mt = 0; mt < 2; mt++) {
                int rb = wm + mt * 16 + g;
                ah[mt][0] = *reinterpret_cast<unsigned*>(&Ah[rb][kb + 2 * cc]);
                ah[mt][1] = *reinterpret_cast<unsigned*>(&Ah[rb + 8][kb + 2 * cc]);
                ah[mt][2] = *reinterpret_cast<unsigned*>(&Ah[rb][kb + 2 * cc + 8]);
                ah[mt][3] = *reinterpret_cast<unsigned*>(&Ah[rb + 8][kb + 2 * cc + 8]);
                al[mt][0] = *reinterpret_cast<unsigned*>(&Al[rb][kb + 2 * cc]);
                al[mt][1] = *reinterpret_cast<unsigned*>(&Al[rb + 8][kb + 2 * cc]);
                al[mt][2] = *reinterpret_cast<unsigned*>(&Al[rb][kb + 2 * cc + 8]);
                al[mt][3] = *reinterpret_cast<unsigned*>(&Al[rb + 8][kb + 2 * cc + 8]);
            }
            unsigned bh[4][2], bl[4][2];
#pragma unroll
            for (int nt = 0; nt < 4; nt++) {
                int nr = wn + nt * 8 + g;
                bh[nt][0] = *reinterpret_cast<unsigned*>(&Bh[nr][kb + 2 * cc]);
                bh[nt][1] = *reinterpret_cast<unsigned*>(&Bh[nr][kb + 2 * cc + 8]);
                bl[nt][0] = *reinterpret_cast<unsigned*>(&Bl[nr][kb + 2 * cc]);
                bl[nt][1] = *reinterpret_cast<unsigned*>(&Bl[nr][kb + 2 * cc + 8]);
            }
#pragma unroll
            for (int mt = 0; mt < 2; mt++)
#pragma unroll
                for (int nt = 0; nt < 4; nt++) {
                    mma_bf16(acc[mt][nt], ah[mt], bh[nt]);
                    mma_bf16(acc[mt][nt], ah[mt], bl[nt]);
                    mma_bf16(acc[mt][nt], al[mt], bh[nt]);
                }
        }
        __syncthreads();
    }

#pragma unroll
    for (int mt = 0; mt < 2; mt++) {
#pragma unroll
        for (int nt = 0; nt < 4; nt++) {
            int col = wn + nt * 8 + 2 * cc;
#pragma unroll
            for (int rr = 0; rr < 2; rr++) {
                int row = m0 + wm + mt * 16 + g + rr * 8;
                if (row >= NN) continue;
                atomicAdd(&g_m[(size_t)row * 64 + col],     acc[mt][nt][rr * 2 + 0]);
                atomicAdd(&g_m[(size_t)row * 64 + col + 1], acc[mt][nt][rr * 2 + 1]);
            }
        }
    }
}

// ---------------- generic tiled SGEMM: C[M,N] = act(A[M,K] * B[N,K]^T + bias) ----------------
template <int BM, int BN, int BK, int TM, int TN, int THREADS, bool RELU>
__global__ __launch_bounds__(THREADS) void sgemm_kernel(
    int a_id, const float* a_ext,
    int b_id, const float* b_ext,
    int bias_id, const float* bias_ext,
    int c_id, float* c_ext,
    int M, int N, int K)
{
    const float* __restrict__ A   = (a_id >= 0) ? g_table[a_id] : a_ext;
    const float* __restrict__ Bw  = (b_id >= 0) ? g_table[b_id] : b_ext;
    const float* __restrict__ bias = (bias_id >= 0) ? g_table[bias_id] : bias_ext;
    float* __restrict__ C = (c_id >= 0) ? g_table[c_id] : c_ext;

    __shared__ float As[BK][BM + 4];
    __shared__ float Bs[BK][BN + 4];

    const int tid = threadIdx.x;
    const int m0 = blockIdx.y * BM;
    const int n0 = blockIdx.x * BN;
    const int NTX = BN / TN;
    const int tx = tid % NTX;
    const int ty = tid / NTX;

    float acc[TM][TN];
#pragma unroll
    for (int i = 0; i < TM; i++)
#pragma unroll
        for (int j = 0; j < TN; j++) acc[i][j] = 0.0f;

    for (int kk = 0; kk < K; kk += BK) {
#pragma unroll
        for (int idx = tid; idx < BM * BK; idx += THREADS) {
            int mm = idx / BK, k = idx % BK;
            int row = m0 + mm, col = kk + k;
            As[k][mm] = (row < M && col < K) ? A[(size_t)row * K + col] : 0.0f;
        }
#pragma unroll
        for (int idx = tid; idx < BN * BK; idx += THREADS) {
            int nn2 = idx / BK, k = idx % BK;
            int row = n0 + nn2, col = kk + k;
            Bs[k][nn2] = (row < N && col < K) ? Bw[(size_t)row * K + col] : 0.0f;
        }
        __syncthreads();

#pragma unroll
        for (int k = 0; k < BK; k++) {
            float a[TM], b[TN];
#pragma unroll
            for (int i = 0; i < TM; i++) a[i] = As[k][ty * TM + i];
#pragma unroll
            for (int j = 0; j < TN; j++) b[j] = Bs[k][tx * TN + j];
#pragma unroll
            for (int i = 0; i < TM; i++)
#pragma unroll
                for (int j = 0; j < TN; j++) acc[i][j] = fmaf(a[i], b[j], acc[i][j]);
        }
        __syncthreads();
    }

#pragma unroll
    for (int i = 0; i < TM; i++) {
        int row = m0 + ty * TM + i;
        if (row >= M) continue;
#pragma unroll
        for (int j = 0; j < TN; j++) {
            int col = n0 + tx * TN + j;
            if (col >= N) continue;
            float v = acc[i][j] + (bias ? bias[col] : 0.0f);
            if (RELU) v = fmaxf(v, 0.0f);
            C[(size_t)row * N + col] = v;
        }
    }
}

// ---------------- edge sort-by-dst ----------------
__global__ void hist_zero_kernel() {
    int i = blockIdx.x * blockDim.x + threadIdx.x;
    if (i < NN) { g_cnt[i] = 0; g_cur[i] = 0; }
}
__global__ void hist_kernel(const int* __restrict__ dst) {
    int e = blockIdx.x * blockDim.x + threadIdx.x;
    if (e >= NE) return;
    int d = dst[e];
    if ((unsigned)d < NN) atomicAdd(&g_cnt[d], 1);
}
__global__ void scan_kernel() {    // 1 block, 1024 threads
    __shared__ int sh[1024];
    __shared__ int carry;
    int tid = threadIdx.x;
    if (tid == 0) carry = 0;
    __syncthreads();
    for (int base = 0; base < NN; base += 1024) {
        int i = base + tid;
        int v = (i < NN) ? g_cnt[i] : 0;
        sh[tid] = v;
        __syncthreads();
        for (int off = 1; off < 1024; off <<= 1) {
            int t = (tid >= off) ? sh[tid - off] : 0;
            __syncthreads();
            sh[tid] += t;
            __syncthreads();
        }
        int c0 = carry;
        int myoff = c0 + sh[tid] - v;
        __syncthreads();
        if (tid == 1023) carry = c0 + sh[1023];
        __syncthreads();
        if (i < NN) g_offs[i] = myoff;
    }
    if (tid == 0) g_offs[NN] = carry;
}
__global__ void scatter_kernel(const int* __restrict__ dst) {
    int e = blockIdx.x * blockDim.x + threadIdx.x;
    if (e >= NE) return;
    int d = dst[e];
    if ((unsigned)d >= NN) return;
    int p = g_offs[d] + atomicAdd(&g_cur[d], 1);
    g_eord[p] = e;
}

// ---------------- Z accumulate: one block per destination node ----------------
__global__ __launch_bounds__(256) void zacc_kernel(const int* __restrict__ src) {
    __shared__ float sh[4][64];
    __shared__ float se[4][64];
    int d = blockIdx.x;
    int beg = g_offs[d], end = g_offs[d + 1];
    int tid = threadIdx.x;
    int i0 = (tid >> 4) << 2;
    int k0 = (tid & 15) << 2;
    float acc[4][4];
#pragma unroll
    for (int r = 0; r < 4; r++)
#pragma unroll
        for (int c = 0; c < 4; c++) acc[r][c] = 0.0f;
    float hs = 0.0f;

    int j = tid >> 6, l = tid & 63;
    for (int p = beg; p < end; p += 4) {
        int nv = end - p;
        if (j < nv) {
            int e = g_eord[p + j];
            int s = src[e];
            sh[j][l] = ((unsigned)s < NN) ? g_h[s * 64 + l] : 0.0f;
            se[j][l] = g_e1[e * 64 + l];
        } else { sh[j][l] = 0.0f; se[j][l] = 0.0f; }
        __syncthreads();
#pragma unroll
        for (int j2 = 0; j2 < 4; j2++) {
            float4 hv = *reinterpret_cast<float4*>(&sh[j2][i0]);
            float4 ev = *reinterpret_cast<float4*>(&se[j2][k0]);
            acc[0][0] = fmaf(hv.x, ev.x, acc[0][0]); acc[0][1] = fmaf(hv.x, ev.y, acc[0][1]);
            acc[0][2] = fmaf(hv.x, ev.z, acc[0][2]); acc[0][3] = fmaf(hv.x, ev.w, acc[0][3]);
            acc[1][0] = fmaf(hv.y, ev.x, acc[1][0]); acc[1][1] = fmaf(hv.y, ev.y, acc[1][1]);
            acc[1][2] = fmaf(hv.y, ev.z, acc[1][2]); acc[1][3] = fmaf(hv.y, ev.w, acc[1][3]);
            acc[2][0] = fmaf(hv.z, ev.x, acc[2][0]); acc[2][1] = fmaf(hv.z, ev.y, acc[2][1]);
            acc[2][2] = fmaf(hv.z, ev.z, acc[2][2]); acc[2][3] = fmaf(hv.z, ev.w, acc[2][3]);
            acc[3][0] = fmaf(hv.w, ev.x, acc[3][0]); acc[3][1] = fmaf(hv.w, ev.y, acc[3][1]);
            acc[3][2] = fmaf(hv.w, ev.z, acc[3][2]); acc[3][3] = fmaf(hv.w, ev.w, acc[3][3]);
        }
        if (tid < 64) hs += sh[0][tid] + sh[1][tid] + sh[2][tid] + sh[3][tid];
        __syncthreads();
    }

    float* Zr = g_zcat + (size_t)d * KZ;
#pragma unroll
    for (int r = 0; r < 4; r++) {
        float4 v = make_float4(acc[r][0], acc[r][1], acc[r][2], acc[r][3]);
        *reinterpret_cast<float4*>(&Zr[(i0 + r) * 64 + k0]) = v;
    }
    if (tid < 64) Zr[4096 + tid] = hs;
}

// ---------------- weight repacks ----------------
__global__ void prep_vcat_kernel(const float* __restrict__ w1c, const float* __restrict__ b1c) {
    int idx = blockIdx.x * blockDim.x + threadIdx.x;
    if (idx >= HD * KZ) return;
    int o = idx / KZ, c = idx % KZ;
    float v;
    if (c < 4096) {
        int i = c >> 6, k = c & 63;
        v = w1c[(i * 64 + o) * 64 + k];
    } else {
        v = b1c[(c - 4096) * 64 + o];
    }
    g_vcat[idx] = v;
}

// ---------------- small kernels ----------------
__global__ void zero_kernel(int id, int n) {
    int i = blockIdx.x * blockDim.x + threadIdx.x;
    if (i < n) g_table[id][i] = 0.0f;
}

__global__ void init_h_kernel(const float* __restrict__ x) {
    int idx = blockIdx.x * blockDim.x + threadIdx.x;
    if (idx >= NN * HD) return;
    int n = idx / HD, c = idx % HD;
    g_h[idx] = (c < NNF) ? x[n * NNF + c] : 0.0f;
}

__global__ void edge_mlp_kernel(const float* __restrict__ ea,
                                const float* __restrict__ w1a, const float* __restrict__ b1a,
                                const float* __restrict__ w1b, const float* __restrict__ b1b)
{
    __shared__ float wa[NEF][HD];
    __shared__ float wb[HD][HD];
    __shared__ float ba[HD], bb[HD];
    __shared__ float s1[4][HD];

    int tid = threadIdx.x;
    for (int i = tid; i < HD * NEF; i += blockDim.x) { int k = i / NEF, f = i % NEF; wa[f][k] = w1a[i]; }
    for (int i = tid; i < HD * HD; i += blockDim.x)  { int k = i / HD,  j = i % HD;  wb[j][k] = w1b[i]; }
    if (tid < HD) { ba[tid] = b1a[tid]; bb[tid] = b1b[tid]; }
    __syncthreads();

    int le = tid >> 6;
    int k  = tid & 63;
    for (int base = blockIdx.x * 4; base < NE; base += gridDim.x * 4) {
        int e = base + le;
        float t1 = ba[k];
#pragma unroll
        for (int f = 0; f < NEF; f++) t1 = fmaf(ea[e * NEF + f], wa[f][k], t1);
        s1[le][k] = fmaxf(t1, 0.0f);
        __syncthreads();
        float t2 = bb[k];
#pragma unroll
        for (int j = 0; j < HD; j++) t2 = fmaf(s1[le][j], wb[j][k], t2);
        g_e1[e * HD + k] = fmaxf(t2, 0.0f);
        __syncthreads();
    }
}

__global__ void gru_pointwise_kernel()
{
    int idx = blockIdx.x * blockDim.x + threadIdx.x;
    if (idx >= NN * HD) return;
    int n = idx / HD, c = idx % HD;
    const float* gi = g_gi + n * 3 * HD;
    const float* gh = g_gh + n * 3 * HD;
    float r = sigf(gi[c] + gh[c]);
    float z = sigf(gi[HD + c] + gh[HD + c]);
    float nn = tanhf(gi[2 * HD + c] + r * gh[2 * HD + c]);
    float h = g_h[idx];
    g_h[idx] = (1.0f - z) * nn + z * h;
}

__global__ void concat_hx_kernel(const float* __restrict__ x)
{
    int idx = blockIdx.x * blockDim.x + threadIdx.x;
    const int W = HD + NNF;
    if (idx >= NN * W) return;
    int n = idx / W, c = idx % W;
    g_hx[idx] = (c < HD) ? g_h[n * HD + c] : x[n * NNF + (c - HD)];
}

__global__ void prep_lstm_kernel(const float* __restrict__ wih0, const float* __restrict__ whh0,
                                 const float* __restrict__ bih0, const float* __restrict__ bhh0,
                                 const float* __restrict__ wih1, const float* __restrict__ whh1,
                                 const float* __restrict__ bih1, const float* __restrict__ bhh1)
{
    int i = blockIdx.x * blockDim.x + threadIdx.x;
    const int n0 = 512 * 384, n1 = 512 * 256;
    if (i < n0) {
        int j = i / 384, c = i % 384;
        g_wcat0[i] = (c < 256) ? wih0[j * 256 + c] : whh0[j * 128 + (c - 256)];
    } else if (i < n0 + n1) {
        int k = i - n0; int j = k / 256, c = k % 256;
        g_wcat1[k] = (c < 128) ? wih1[j * 128 + c] : whh1[j * 128 + (c - 128)];
    } else if (i < n0 + n1 + 512) {
        int j = i - n0 - n1; g_bs0[j] = bih0[j] + bhh0[j];
    } else if (i < n0 + n1 + 1024) {
        int j = i - n0 - n1 - 512; g_bs1[j] = bih1[j] + bhh1[j];
    }
}

__global__ void seg_init_kernel() {
    int b = blockIdx.x * blockDim.x + threadIdx.x;
    if (b < BG) { g_gs[b] = NN; g_ge[b] = 0; }
}
__global__ void seg_mark_kernel(const int* __restrict__ batch) {
    int n = blockIdx.x * blockDim.x + threadIdx.x;
    if (n >= NN) return;
    int b = batch[n];
    if ((unsigned)b >= BG) return;
    atomicMin(&g_gs[b], n);
    atomicMax(&g_ge[b], n + 1);
}

__global__ void lstm_in0_kernel() {
    int idx = blockIdx.x * blockDim.x + threadIdx.x;
    if (idx >= BG * 384) return;
    int b = idx / 384, c = idx % 384;
    g_lin0[idx] = (c < 256) ? g_qstar[b * 256 + c] : g_h0[b * 128 + (c - 256)];
}
__global__ void lstm_in1_kernel() {
    int idx = blockIdx.x * blockDim.x + threadIdx.x;
    if (idx >= BG * 256) return;
    int b = idx / 256, c = idx % 256;
    g_lin1[idx] = (c < 128) ? g_h0[b * 128 + c] : g_h1[b * 128 + (c - 128)];
}

__global__ void lstm_pw_kernel(int h_id, int c_id)
{
    float* __restrict__ h = g_table[h_id];
    float* __restrict__ c = g_table[c_id];
    int idx = blockIdx.x * blockDim.x + threadIdx.x;
    if (idx >= BG * IC) return;
    int b = idx / IC, d = idx % IC;
    const float* g = g_gates + b * 512;
    float gi = g[d], gf = g[128 + d], gg = g[256 + d], go = g[384 + d];
    float cn = sigf(gf) * c[idx] + sigf(gi) * tanhf(gg);
    c[idx] = cn;
    h[idx] = sigf(go) * tanhf(cn);
}

__global__ void attn_dot_kernel(const int* __restrict__ batch)
{
    int w = (blockIdx.x * blockDim.x + threadIdx.x) >> 5;
    int lane = threadIdx.x & 31;
    if (w >= NN) return;
    int b = batch[w];
    if ((unsigned)b >= BG) { if (lane == 0) g_eatt[w] = 0.0f; return; }
    float4 a = reinterpret_cast<const float4*>(g_h2 + (size_t)w * IC)[lane];
    float4 q = reinterpret_cast<const float4*>(g_h1 + (size_t)b * IC)[lane];
    float s = a.x * q.x + a.y * q.y + a.z * q.z + a.w * q.w;
#pragma unroll
    for (int o = 16; o > 0; o >>= 1) s += __shfl_xor_sync(0xffffffffu, s, o);
    if (lane == 0) g_eatt[w] = s;
}

__global__ void attn_reduce_kernel()
{
    __shared__ float red[128];
    int b = blockIdx.x;
    int s = g_gs[b], e = g_ge[b];
    int tid = threadIdx.x;

    float mx = -1e30f;
    for (int n = s + tid; n < e; n += 128) mx = fmaxf(mx, g_eatt[n]);
    red[tid] = mx;
    __syncthreads();
    for (int o = 64; o > 0; o >>= 1) {
        if (tid < o) red[tid] = fmaxf(red[tid], red[tid + o]);
        __syncthreads();
    }
    float m = red[0];

    float rd = 0.0f, den = 0.0f;
    for (int n = s; n < e; n++) {
        float a = expf(g_eatt[n] - m);
        den += a;
        rd = fmaf(a, g_h2[(size_t)n * IC + tid], rd);
    }
    g_qstar[b * 256 + 128 + tid] = (den > 0.0f) ? (rd / den) : 0.0f;
    g_qstar[b * 256 + tid] = g_h1[b * IC + tid];
}

// ---------------- host orchestration ----------------
extern "C" void kernel_launch(void* const* d_in, const int* in_sizes, int n_in,
                              void* d_out, int out_size)
{
    const float *x = 0, *ea = 0, *w1a = 0, *b1a = 0, *w1b = 0, *b1b = 0, *w1c = 0, *b1c = 0;
    const float *gwih = 0, *gwhh = 0, *gbih = 0, *gbhh = 0, *linw = 0, *linb = 0;
    const float *lwih0 = 0, *lwhh0 = 0, *lbih0 = 0, *lbhh0 = 0;
    const float *lwih1 = 0, *lwhh1 = 0, *lbih1 = 0, *lbhh1 = 0;
    const float *w2a = 0, *b2a = 0, *w2b = 0, *b2b = 0;
    const int *eidx = 0, *batch = 0;

    int c64 = 0, c4096 = 0, c12288 = 0, c192 = 0, c131072 = 0, c65536 = 0, c512 = 0;
    for (int i = 0; i < n_in; i++) {
        const void* p = d_in[i];
        int s = in_sizes[i];
        if      (s == 110000) x = (const float*)p;
        else if (s == 200000) ea = (const float*)p;
        else if (s == 100000) eidx = (const int*)p;
        else if (s == 10000)  batch = (const int*)p;
        else if (s == 1)      { }
        else if (s == 256)    w1a = (const float*)p;
        else if (s == 64)     { if (c64++ == 0) b1a = (const float*)p; else b1b = (const float*)p; }
        else if (s == 4096)   { if (c4096++ == 0) w1b = (const float*)p; else b1c = (const float*)p; }
        else if (s == 262144) w1c = (const float*)p;
        else if (s == 12288)  { if (c12288++ == 0) gwih = (const float*)p; else gwhh = (const float*)p; }
        else if (s == 192)    { if (c192++ == 0) gbih = (const float*)p; else gbhh = (const float*)p; }
        else if (s == 9600)   linw = (const float*)p;
        else if (s == 128)    linb = (const float*)p;
        else if (s == 131072) { if (c131072++ == 0) lwih0 = (const float*)p; else w2a = (const float*)p; }
        else if (s == 65536)  { int k = c65536++; if (k == 0) lwhh0 = (const float*)p;
                                else if (k == 1) lwih1 = (const float*)p; else lwhh1 = (const float*)p; }
        else if (s == 512)    { int k = c512++;
                                if (k == 0) lbih0 = (const float*)p;
                                else if (k == 1) lbhh0 = (const float*)p;
                                else if (k == 2) lbih1 = (const float*)p;
                                else if (k == 3) lbhh1 = (const float*)p;
                                else b2a = (const float*)p; }
        else if (s == 6144)   w2b = (const float*)p;
        else if (s == 12)     b2b = (const float*)p;
    }
    float* out = (float*)d_out;
    const int* src = eidx;
    const int* dst = eidx + NE;

    setup_ptrs_kernel<<<1, 1>>>();

    // h init + edge MLP + Vcat repack
    init_h_kernel<<<(NN * HD + 255) / 256, 256>>>(x);
    edge_mlp_kernel<<<256, 256>>>(ea, w1a, b1a, w1b, b1b);
    prep_vcat_kernel<<<(HD * KZ + 255) / 256, 256>>>(w1c, b1c);

    // sort edges by dst
    hist_zero_kernel<<<(NN + 255) / 256, 256>>>();
    hist_kernel<<<(NE + 255) / 256, 256>>>(dst);
    scan_kernel<<<1, 1024>>>();
    scatter_kernel<<<(NE + 255) / 256, 256>>>(dst);

    // set2set prep (independent)
    prep_lstm_kernel<<<(512 * 384 + 512 * 256 + 1024 + 255) / 256, 256>>>(
        lwih0, lwhh0, lbih0, lbhh0, lwih1, lwhh1, lbih1, lbhh1);
    seg_init_kernel<<<1, 256>>>();
    seg_mark_kernel<<<(NN + 255) / 256, 256>>>(batch);

    const int MB128 = (NN + 127) / 128;   // 79

    // T message-passing steps: Z-accumulate -> bf16 tensor zgemm -> GRU
    for (int t = 0; t < 3; t++) {
        zacc_kernel<<<NN, 256>>>(src);
        zero_kernel<<<(NN * HD + 255) / 256, 256>>>(ID_M, NN * HD);
        {
            dim3 grid(1, MB128, 4);   // K-split 4: 316 CTAs, ~2/SM
            zgemm_bf16_kernel<<<grid, 256>>>(4);
        }
        {
            dim3 grid((3 * HD + 63) / 64, (NN + 63) / 64);
            sgemm_kernel<64, 64, 16, 4, 4, 256, false><<<grid, 256>>>(
                ID_M, nullptr, -1, gwih, -1, gbih, ID_GI, nullptr, NN, 3 * HD, HD);
            sgemm_kernel<64, 64, 16, 4, 4, 256, false><<<grid, 256>>>(
                ID_H, nullptr, -1, gwhh, -1, gbhh, ID_GH, nullptr, NN, 3 * HD, HD);
        }
        gru_pointwise_kernel<<<(NN * HD + 255) / 256, 256>>>();
    }

    // lin: h2 = [h|x] @ lin_w^T + lin_b  (K=75)
    concat_hx_kernel<<<(NN * (HD + NNF) + 255) / 256, 256>>>(x);
    {
        dim3 grid((IC + 63) / 64, (NN + 63) / 64);
        sgemm_kernel<64, 64, 16, 4, 4, 256, false><<<grid, 256>>>(
            ID_HX, nullptr, -1, linw, -1, linb, ID_H2, nullptr, NN, IC, HD + NNF);
    }

    // Set2Set
    zero_kernel<<<(BG * 256 + 255) / 256, 256>>>(ID_QSTAR, BG * 256);
    zero_kernel<<<(BG * IC + 255) / 256, 256>>>(ID_H0, BG * IC);
    zero_kernel<<<(BG * IC + 255) / 256, 256>>>(ID_C0, BG * IC);
    zero_kernel<<<(BG * IC + 255) / 256, 256>>>(ID_H1, BG * IC);
    zero_kernel<<<(BG * IC + 255) / 256, 256>>>(ID_C1, BG * IC);

    for (int ms = 0; ms < 3; ms++) {
        lstm_in0_kernel<<<(BG * 384 + 255) / 256, 256>>>();
        {
            dim3 grid((512 + 63) / 64, (BG + 31) / 32);
            sgemm_kernel<32, 64, 16, 2, 4, 256, false><<<grid, 256>>>(
                ID_LIN0, nullptr, ID_WCAT0, nullptr, ID_BS0, nullptr, ID_GATES, nullptr,
                BG, 512, 384);
        }
        lstm_pw_kernel<<<(BG * IC + 255) / 256, 256>>>(ID_H0, ID_C0);

        lstm_in1_kernel<<<(BG * 256 + 255) / 256, 256>>>();
        {
            dim3 grid((512 + 63) / 64, (BG + 31) / 32);
            sgemm_kernel<32, 64, 16, 2, 4, 256, false><<<grid, 256>>>(
                ID_LIN1, nullptr, ID_WCAT1, nullptr, ID_BS1, nullptr, ID_GATES, nullptr,
                BG, 512, 256);
        }
        lstm_pw_kernel<<<(BG * IC + 255) / 256, 256>>>(ID_H1, ID_C1);

        attn_dot_kernel<<<(NN * 32 + 255) / 256, 256>>>(batch);
        attn_reduce_kernel<<<BG, 128>>>();
    }

    // output MLP
    {
        dim3 grid1((512 + 63) / 64, (BG + 31) / 32);
        sgemm_kernel<32, 64, 16, 2, 4, 256, true><<<grid1, 256>>>(
            ID_QSTAR, nullptr, -1, w2a, -1, b2a, ID_T2A, nullptr, BG, 512, 256);
        dim3 grid2(1, (BG + 31) / 32);
        sgemm_kernel<32, 64, 16, 2, 4, 256, false><<<grid2, 256>>>(
            ID_T2A, nullptr, -1, w2b, -1, b2b, -1, out, BG, NTG, 512);
    }
}